// round 1
// baseline (speedup 1.0000x reference)
#include <cuda_runtime.h>

// ---------------- problem constants (fixed by reference) ----------------
#define NN   50000
#define NE   1600000
#define NEP  (NE + NN)      // edges + self loops
#define KDIM 256            // DIN and HID
#define HC   128            // HEADS*C per direction
#define NEG  0.2f

// ---------------- device scratch (no allocs allowed) ----------------
__device__ float g_xl_f[NN * HC];
__device__ float g_xl_b[NN * HC];
__device__ float g_al_f[NN * 4];
__device__ float g_ar_f[NN * 4];
__device__ float g_al_b[NN * 4];
__device__ float g_ar_b[NN * 4];
__device__ float g_den_f[NN * 4];
__device__ float g_den_b[NN * 4];
__device__ float g_agg_f[NN * HC];
__device__ float g_agg_b[NN * HC];
__device__ float g_Wcat[KDIM * 256];   // [k][j], j<128 -> W_f, else W_b
__device__ float g_scale[256];
__device__ float g_shift[256];

__device__ __forceinline__ float lrelu(float v) { return v > 0.f ? v : NEG * v; }

// ---------------- small prep kernels ----------------
__global__ void pack_kernel(const float* __restrict__ Wf, const float* __restrict__ Wb,
                            const float* __restrict__ b_fuse,
                            const float* __restrict__ gamma, const float* __restrict__ beta,
                            const float* __restrict__ mean, const float* __restrict__ var) {
    int t = blockIdx.x * blockDim.x + threadIdx.x;
    if (t < KDIM * 256) {
        int k = t >> 8, j = t & 255;
        g_Wcat[t] = (j < HC) ? Wf[k * HC + j] : Wb[k * HC + (j - HC)];
    }
    if (t < 256) {
        float inv = rsqrtf(var[t] + 1e-5f);
        float sc = gamma[t] * inv;
        g_scale[t] = sc;
        g_shift[t] = beta[t] + (b_fuse[t] - mean[t]) * sc;
    }
}

__global__ void init_kernel(const float* __restrict__ b_f, const float* __restrict__ b_b) {
    int t = blockIdx.x * blockDim.x + threadIdx.x;
    if (t >= NN * HC) return;
    int c = t & (HC - 1);
    g_agg_f[t] = b_f[c];   // bias folded into aggregate init
    g_agg_b[t] = b_b[c];
    if (c < 4) {
        int n = t >> 7;
        g_den_f[n * 4 + c] = 0.f;
        g_den_b[n * 4 + c] = 0.f;
    }
}

// ---------------- SGEMM: 128x128 tile, 8x8 per thread, BK=16 ----------------
// MODE 0: C = A[NN,256] @ g_Wcat  -> split into g_xl_f / g_xl_b
// MODE 1: C = concat(g_agg_f,g_agg_b)[NN,256] @ B(W_fuse) -> BN+ReLU -> out
template <int MODE>
__global__ void __launch_bounds__(256)
sgemm_kernel(const float* __restrict__ A, const float* __restrict__ B,
             float* __restrict__ Cout) {
    constexpr int BM = 128, BN = 128, BK = 16;
    __shared__ float As[BK][BM + 4];
    __shared__ float Bs[BK][BN + 4];
    const int tid = threadIdx.x;
    const int row0 = blockIdx.x * BM;
    const int col0 = blockIdx.y * BN;
    const int tx = tid & 15, ty = tid >> 4;

    float acc[8][8];
#pragma unroll
    for (int i = 0; i < 8; i++)
#pragma unroll
        for (int j = 0; j < 8; j++) acc[i][j] = 0.f;

    const float* Bp = (MODE == 0) ? g_Wcat : B;

    for (int kt = 0; kt < KDIM; kt += BK) {
        // load A tile [BM x BK], store transposed
#pragma unroll
        for (int l = 0; l < 2; l++) {
            int v = tid + l * 256;
            int r = v >> 2;
            int c4 = (v & 3) << 2;
            int grow = row0 + r;
            float4 val = make_float4(0.f, 0.f, 0.f, 0.f);
            if (grow < NN) {
                int gk = kt + c4;
                if (MODE == 0) {
                    val = *(const float4*)(A + (size_t)grow * KDIM + gk);
                } else {
                    const float* ap = (gk < HC) ? (g_agg_f + (size_t)grow * HC + gk)
                                                : (g_agg_b + (size_t)grow * HC + (gk - HC));
                    val = *(const float4*)ap;
                }
            }
            As[c4 + 0][r] = val.x;
            As[c4 + 1][r] = val.y;
            As[c4 + 2][r] = val.z;
            As[c4 + 3][r] = val.w;
        }
        // load B tile [BK x BN]
#pragma unroll
        for (int l = 0; l < 2; l++) {
            int v = tid + l * 256;
            int r = v >> 5;
            int c4 = (v & 31) << 2;
            *(float4*)&Bs[r][c4] = *(const float4*)(Bp + (size_t)(kt + r) * 256 + col0 + c4);
        }
        __syncthreads();
#pragma unroll
        for (int k = 0; k < BK; k++) {
            float am[8], bn[8];
#pragma unroll
            for (int i = 0; i < 8; i++) am[i] = As[k][ty * 8 + i];
#pragma unroll
            for (int j = 0; j < 8; j++) bn[j] = Bs[k][tx * 8 + j];
#pragma unroll
            for (int i = 0; i < 8; i++)
#pragma unroll
                for (int j = 0; j < 8; j++) acc[i][j] = fmaf(am[i], bn[j], acc[i][j]);
        }
        __syncthreads();
    }

#pragma unroll
    for (int i = 0; i < 8; i++) {
        int grow = row0 + ty * 8 + i;
        if (grow >= NN) continue;
#pragma unroll
        for (int j = 0; j < 8; j += 4) {
            int gcol = col0 + tx * 8 + j;
            float4 v = make_float4(acc[i][j], acc[i][j + 1], acc[i][j + 2], acc[i][j + 3]);
            if (MODE == 0) {
                if (gcol < HC)
                    *(float4*)(g_xl_f + (size_t)grow * HC + gcol) = v;
                else
                    *(float4*)(g_xl_b + (size_t)grow * HC + (gcol - HC)) = v;
            } else {
                float4 sc = *(const float4*)(g_scale + gcol);
                float4 sh = *(const float4*)(g_shift + gcol);
                v.x = fmaxf(fmaf(v.x, sc.x, sh.x), 0.f);
                v.y = fmaxf(fmaf(v.y, sc.y, sh.y), 0.f);
                v.z = fmaxf(fmaf(v.z, sc.z, sh.z), 0.f);
                v.w = fmaxf(fmaf(v.w, sc.w, sh.w), 0.f);
                *(float4*)(Cout + (size_t)grow * 256 + gcol) = v;
            }
        }
    }
}

// ---------------- per-(node,head) attention logits ----------------
__global__ void alar_kernel(const float* __restrict__ a_src_f, const float* __restrict__ a_dst_f,
                            const float* __restrict__ a_src_b, const float* __restrict__ a_dst_b) {
    int t = blockIdx.x * blockDim.x + threadIdx.x;
    if (t >= NN * 4) return;
    int n = t >> 2, h = t & 3;
    const float4* xf = (const float4*)(g_xl_f + (size_t)n * HC + h * 32);
    const float4* xb = (const float4*)(g_xl_b + (size_t)n * HC + h * 32);
    const float4* asf = (const float4*)(a_src_f + h * 32);
    const float4* adf = (const float4*)(a_dst_f + h * 32);
    const float4* asb = (const float4*)(a_src_b + h * 32);
    const float4* adb = (const float4*)(a_dst_b + h * 32);
    float sf = 0.f, df = 0.f, sb = 0.f, db = 0.f;
#pragma unroll
    for (int i = 0; i < 8; i++) {
        float4 v = xf[i], a = asf[i], d = adf[i];
        sf += v.x * a.x + v.y * a.y + v.z * a.z + v.w * a.w;
        df += v.x * d.x + v.y * d.y + v.z * d.z + v.w * d.w;
        float4 vb = xb[i], ab = asb[i], dbv = adb[i];
        sb += vb.x * ab.x + vb.y * ab.y + vb.z * ab.z + vb.w * ab.w;
        db += vb.x * dbv.x + vb.y * dbv.y + vb.z * dbv.z + vb.w * dbv.w;
    }
    g_al_f[t] = sf;
    g_ar_f[t] = df;
    g_al_b[t] = sb;
    g_ar_b[t] = db;
}

// ---------------- edge pass 1: softmax denominators (no max-shift needed) ----------------
__global__ void edge_den_kernel(const int* __restrict__ ei) {
    int idx = blockIdx.x * blockDim.x + threadIdx.x;
    if (idx >= NEP) return;
    int s, d;
    if (idx < NE) {
        s = __ldg(&ei[idx]);
        d = __ldg(&ei[NE + idx]);
    } else {
        s = d = idx - NE;
    }
    // forward: e = lrelu(al_f[s] + ar_f[d]), aggregate at d
    float4 a = *(const float4*)(g_al_f + s * 4);
    float4 b = *(const float4*)(g_ar_f + d * 4);
    float4 w;
    w.x = __expf(lrelu(a.x + b.x));
    w.y = __expf(lrelu(a.y + b.y));
    w.z = __expf(lrelu(a.z + b.z));
    w.w = __expf(lrelu(a.w + b.w));
    atomicAdd((float4*)(g_den_f + d * 4), w);
    // backward (reversed edges): e = lrelu(al_b[d] + ar_b[s]), aggregate at s
    float4 ab = *(const float4*)(g_al_b + d * 4);
    float4 bb = *(const float4*)(g_ar_b + s * 4);
    float4 wb;
    wb.x = __expf(lrelu(ab.x + bb.x));
    wb.y = __expf(lrelu(ab.y + bb.y));
    wb.z = __expf(lrelu(ab.z + bb.z));
    wb.w = __expf(lrelu(ab.w + bb.w));
    atomicAdd((float4*)(g_den_b + s * 4), wb);
}

// ---------------- edge pass 2: weighted message scatter (warp per edge) ----------------
__global__ void edge_msg_kernel(const int* __restrict__ ei) {
    int gt = blockIdx.x * blockDim.x + threadIdx.x;
    int widx = gt >> 5;
    int lane = gt & 31;
    if (widx >= NEP) return;
    int s, d;
    if (widx < NE) {
        s = __ldg(&ei[widx]);
        d = __ldg(&ei[NE + widx]);
    } else {
        s = d = widx - NE;
    }
    int h = lane >> 3;  // lane's head (4 channels per lane, 8 lanes per head)
    // forward
    {
        float e = lrelu(__ldg(&g_al_f[s * 4 + h]) + __ldg(&g_ar_f[d * 4 + h]));
        float alpha = __expf(e) / (__ldg(&g_den_f[d * 4 + h]) + 1e-16f);
        float4 v = *(const float4*)(g_xl_f + (size_t)s * HC + lane * 4);
        v.x *= alpha; v.y *= alpha; v.z *= alpha; v.w *= alpha;
        atomicAdd((float4*)(g_agg_f + (size_t)d * HC + lane * 4), v);
    }
    // backward
    {
        float e = lrelu(__ldg(&g_al_b[d * 4 + h]) + __ldg(&g_ar_b[s * 4 + h]));
        float alpha = __expf(e) / (__ldg(&g_den_b[s * 4 + h]) + 1e-16f);
        float4 v = *(const float4*)(g_xl_b + (size_t)d * HC + lane * 4);
        v.x *= alpha; v.y *= alpha; v.z *= alpha; v.w *= alpha;
        atomicAdd((float4*)(g_agg_b + (size_t)s * HC + lane * 4), v);
    }
}

// ---------------- launch ----------------
extern "C" void kernel_launch(void* const* d_in, const int* in_sizes, int n_in,
                              void* d_out, int out_size) {
    const float* x        = (const float*)d_in[0];
    const int*   ei       = (const int*)d_in[1];
    const float* W_f      = (const float*)d_in[2];
    const float* a_src_f  = (const float*)d_in[3];
    const float* a_dst_f  = (const float*)d_in[4];
    const float* b_f      = (const float*)d_in[5];
    const float* W_b      = (const float*)d_in[6];
    const float* a_src_b  = (const float*)d_in[7];
    const float* a_dst_b  = (const float*)d_in[8];
    const float* b_b      = (const float*)d_in[9];
    const float* W_fuse   = (const float*)d_in[10];
    const float* b_fuse   = (const float*)d_in[11];
    const float* gamma    = (const float*)d_in[12];
    const float* beta     = (const float*)d_in[13];
    const float* run_mean = (const float*)d_in[14];
    const float* run_var  = (const float*)d_in[15];
    float* out = (float*)d_out;

    pack_kernel<<<(KDIM * 256 + 255) / 256, 256>>>(W_f, W_b, b_fuse, gamma, beta,
                                                   run_mean, run_var);
    init_kernel<<<(NN * HC + 255) / 256, 256>>>(b_f, b_b);

    dim3 gg((NN + 127) / 128, 2);
    sgemm_kernel<0><<<gg, 256>>>(x, nullptr, nullptr);

    alar_kernel<<<(NN * 4 + 255) / 256, 256>>>(a_src_f, a_dst_f, a_src_b, a_dst_b);

    edge_den_kernel<<<(NEP + 255) / 256, 256>>>(ei);

    int msg_threads_blocks = (NEP * 32 + 255) / 256;
    edge_msg_kernel<<<msg_threads_blocks, 256>>>(ei);

    sgemm_kernel<1><<<gg, 256>>>(nullptr, W_fuse, out);
}

// round 2
// speedup vs baseline: 1.3417x; 1.3417x over previous
#include <cuda_runtime.h>

// ---------------- problem constants ----------------
#define NN   50000
#define NE   1600000
#define NEP  (NE + NN)      // edges + self loops
#define KDIM 256
#define HC   128
#define NEG  0.2f

// ---------------- device scratch ----------------
__device__ float g_xl_f[NN * HC];
__device__ float g_xl_b[NN * HC];
__device__ float g_al_f[NN * 4];
__device__ float g_ar_f[NN * 4];
__device__ float g_al_b[NN * 4];
__device__ float g_ar_b[NN * 4];
__device__ float g_agg_f[NN * HC];
__device__ float g_agg_b[NN * HC];
__device__ float g_scale[256];
__device__ float g_shift[256];
// CSR scratch
__device__ int g_deg_in[NN];
__device__ int g_deg_out[NN];
__device__ int g_off_in[NN];
__device__ int g_off_out[NN];
__device__ int g_cur_in[NN];
__device__ int g_cur_out[NN];
__device__ int g_in_src[NEP];   // sorted by dst: source node per in-edge
__device__ int g_out_dst[NEP];  // sorted by src: dest node per out-edge

__device__ __forceinline__ float lrelu(float v) { return v > 0.f ? v : NEG * v; }

__device__ __forceinline__ unsigned long long pack2(float x, float y) {
    unsigned long long r;
    asm("mov.b64 %0, {%1, %2};" : "=l"(r) : "f"(x), "f"(y));
    return r;
}
__device__ __forceinline__ void unpack2(float& x, float& y, unsigned long long v) {
    asm("mov.b64 {%0, %1}, %2;" : "=f"(x), "=f"(y) : "l"(v));
}
__device__ __forceinline__ unsigned long long fma2(unsigned long long a, unsigned long long b,
                                                   unsigned long long c) {
    unsigned long long d;
    asm("fma.rn.f32x2 %0, %1, %2, %3;" : "=l"(d) : "l"(a), "l"(b), "l"(c));
    return d;
}

// ---------------- prep: BN constants + zero degree arrays ----------------
__global__ void pack_kernel(const float* __restrict__ b_fuse,
                            const float* __restrict__ gamma, const float* __restrict__ beta,
                            const float* __restrict__ mean, const float* __restrict__ var) {
    int t = blockIdx.x * blockDim.x + threadIdx.x;
    if (t < NN) { g_deg_in[t] = 0; g_deg_out[t] = 0; }
    if (t < 256) {
        float inv = rsqrtf(var[t] + 1e-5f);
        float sc = gamma[t] * inv;
        g_scale[t] = sc;
        g_shift[t] = beta[t] + (b_fuse[t] - mean[t]) * sc;
    }
}

// ---------------- CSR build ----------------
__global__ void hist_kernel(const int* __restrict__ ei) {
    int idx = blockIdx.x * blockDim.x + threadIdx.x;
    if (idx >= NEP) return;
    int s, d;
    if (idx < NE) { s = __ldg(&ei[idx]); d = __ldg(&ei[NE + idx]); }
    else          { s = d = idx - NE; }
    atomicAdd(&g_deg_in[d], 1);
    atomicAdd(&g_deg_out[s], 1);
}

__global__ void scan_kernel() {
    __shared__ int part[1024];
    int* deg = blockIdx.x ? g_deg_out : g_deg_in;
    int* off = blockIdx.x ? g_off_out : g_off_in;
    int* cur = blockIdx.x ? g_cur_out : g_cur_in;
    int t = threadIdx.x;
    const int CH = (NN + 1023) / 1024;  // 49
    int base = t * CH;
    int s = 0;
    for (int i = 0; i < CH; i++) { int idx = base + i; if (idx < NN) s += deg[idx]; }
    part[t] = s;
    __syncthreads();
    for (int d = 1; d < 1024; d <<= 1) {
        int v = (t >= d) ? part[t - d] : 0;
        __syncthreads();
        part[t] += v;
        __syncthreads();
    }
    int pre = (t == 0) ? 0 : part[t - 1];
    for (int i = 0; i < CH; i++) {
        int idx = base + i;
        if (idx < NN) { off[idx] = pre; cur[idx] = pre; pre += deg[idx]; }
    }
}

__global__ void scatter_kernel(const int* __restrict__ ei) {
    int idx = blockIdx.x * blockDim.x + threadIdx.x;
    if (idx >= NEP) return;
    int s, d;
    if (idx < NE) { s = __ldg(&ei[idx]); d = __ldg(&ei[NE + idx]); }
    else          { s = d = idx - NE; }
    int p = atomicAdd(&g_cur_in[d], 1);
    g_in_src[p] = s;
    int q = atomicAdd(&g_cur_out[s], 1);
    g_out_dst[q] = d;
}

// ---------------- SGEMM 128x128x16, 8x8/thread, f32x2 packed FMA ----------------
// MODE 0: C = x[NN,256] @ W_{f|b} (blockIdx.y selects) -> g_xl_*, fused al/ar epilogue
// MODE 1: C = concat(agg_f,agg_b) @ W_fuse -> BN+ReLU -> out
template <int MODE>
__global__ void __launch_bounds__(256)
sgemm_kernel(const float* __restrict__ A, const float* __restrict__ Bf,
             const float* __restrict__ Bb, float* __restrict__ Cout,
             const float* __restrict__ asrc_f, const float* __restrict__ adst_f,
             const float* __restrict__ asrc_b, const float* __restrict__ adst_b) {
    constexpr int BM = 128, BN = 128, BK = 16;
    __shared__ float As[BK][BM + 4];
    __shared__ float Bs[BK][BN + 4];
    const int tid = threadIdx.x;
    const int row0 = blockIdx.x * BM;
    const int col0 = blockIdx.y * BN;
    const int tx = tid & 15, ty = tid >> 4;

    unsigned long long acc2[8][4];
    const unsigned long long Z = pack2(0.f, 0.f);
#pragma unroll
    for (int i = 0; i < 8; i++)
#pragma unroll
        for (int j = 0; j < 4; j++) acc2[i][j] = Z;

    const float* Bp = (MODE == 0) ? ((blockIdx.y == 0) ? Bf : Bb) : Bf;

    for (int kt = 0; kt < KDIM; kt += BK) {
#pragma unroll
        for (int l = 0; l < 2; l++) {
            int v = tid + l * 256;
            int r = v >> 2;
            int c4 = (v & 3) << 2;
            int grow = row0 + r;
            float4 val = make_float4(0.f, 0.f, 0.f, 0.f);
            if (grow < NN) {
                int gk = kt + c4;
                if (MODE == 0) {
                    val = *(const float4*)(A + (size_t)grow * KDIM + gk);
                } else {
                    const float* ap = (gk < HC) ? (g_agg_f + (size_t)grow * HC + gk)
                                                : (g_agg_b + (size_t)grow * HC + (gk - HC));
                    val = *(const float4*)ap;
                }
            }
            As[c4 + 0][r] = val.x;
            As[c4 + 1][r] = val.y;
            As[c4 + 2][r] = val.z;
            As[c4 + 3][r] = val.w;
        }
#pragma unroll
        for (int l = 0; l < 2; l++) {
            int v = tid + l * 256;
            int r = v >> 5;
            int c4 = (v & 31) << 2;
            float4 bv;
            if (MODE == 0)
                bv = *(const float4*)(Bp + (size_t)(kt + r) * HC + c4);
            else
                bv = *(const float4*)(Bp + (size_t)(kt + r) * 256 + col0 + c4);
            *(float4*)&Bs[r][c4] = bv;
        }
        __syncthreads();
#pragma unroll
        for (int k = 0; k < BK; k++) {
            float4 a0 = *(const float4*)&As[k][ty * 8];
            float4 a1 = *(const float4*)&As[k][ty * 8 + 4];
            float4 b0 = *(const float4*)&Bs[k][tx * 8];
            float4 b1 = *(const float4*)&Bs[k][tx * 8 + 4];
            unsigned long long bp[4] = {pack2(b0.x, b0.y), pack2(b0.z, b0.w),
                                        pack2(b1.x, b1.y), pack2(b1.z, b1.w)};
            float am[8] = {a0.x, a0.y, a0.z, a0.w, a1.x, a1.y, a1.z, a1.w};
#pragma unroll
            for (int i = 0; i < 8; i++) {
                unsigned long long aa = pack2(am[i], am[i]);
#pragma unroll
                for (int j = 0; j < 4; j++) acc2[i][j] = fma2(aa, bp[j], acc2[i][j]);
            }
        }
        __syncthreads();
    }

    float accf[8][8];
#pragma unroll
    for (int i = 0; i < 8; i++)
#pragma unroll
        for (int j = 0; j < 4; j++) unpack2(accf[i][2 * j], accf[i][2 * j + 1], acc2[i][j]);

    if (MODE == 0) {
        float* xl = (blockIdx.y == 0) ? g_xl_f : g_xl_b;
        const float* asrc = (blockIdx.y == 0) ? asrc_f : asrc_b;
        const float* adst = (blockIdx.y == 0) ? adst_f : adst_b;
        float* alp = (blockIdx.y == 0) ? g_al_f : g_al_b;
        float* arp = (blockIdx.y == 0) ? g_ar_f : g_ar_b;
        float av[8], dv[8];
        *(float4*)&av[0] = *(const float4*)(asrc + tx * 8);
        *(float4*)&av[4] = *(const float4*)(asrc + tx * 8 + 4);
        *(float4*)&dv[0] = *(const float4*)(adst + tx * 8);
        *(float4*)&dv[4] = *(const float4*)(adst + tx * 8 + 4);
        int head = tx >> 2;
#pragma unroll
        for (int i = 0; i < 8; i++) {
            int grow = row0 + ty * 8 + i;
            float ps = 0.f, pd = 0.f;
#pragma unroll
            for (int j = 0; j < 8; j++) {
                ps = fmaf(accf[i][j], av[j], ps);
                pd = fmaf(accf[i][j], dv[j], pd);
            }
            ps += __shfl_xor_sync(0xffffffffu, ps, 1);
            pd += __shfl_xor_sync(0xffffffffu, pd, 1);
            ps += __shfl_xor_sync(0xffffffffu, ps, 2);
            pd += __shfl_xor_sync(0xffffffffu, pd, 2);
            if (grow < NN) {
                *(float4*)(xl + (size_t)grow * HC + tx * 8) =
                    make_float4(accf[i][0], accf[i][1], accf[i][2], accf[i][3]);
                *(float4*)(xl + (size_t)grow * HC + tx * 8 + 4) =
                    make_float4(accf[i][4], accf[i][5], accf[i][6], accf[i][7]);
                if ((tx & 3) == 0) {
                    alp[grow * 4 + head] = ps;
                    arp[grow * 4 + head] = pd;
                }
            }
        }
    } else {
#pragma unroll
        for (int i = 0; i < 8; i++) {
            int grow = row0 + ty * 8 + i;
            if (grow >= NN) continue;
#pragma unroll
            for (int j = 0; j < 8; j += 4) {
                int gcol = col0 + tx * 8 + j;
                float4 sc = *(const float4*)(g_scale + gcol);
                float4 sh = *(const float4*)(g_shift + gcol);
                float4 v;
                v.x = fmaxf(fmaf(accf[i][j + 0], sc.x, sh.x), 0.f);
                v.y = fmaxf(fmaf(accf[i][j + 1], sc.y, sh.y), 0.f);
                v.z = fmaxf(fmaf(accf[i][j + 2], sc.z, sh.z), 0.f);
                v.w = fmaxf(fmaf(accf[i][j + 3], sc.w, sh.w), 0.f);
                *(float4*)(Cout + (size_t)grow * 256 + gcol) = v;
            }
        }
    }
}

// ---------------- gather: warp per (node, direction), single pass ----------------
__global__ void __launch_bounds__(256)
gather_kernel(const float* __restrict__ b_f, const float* __restrict__ b_b) {
    int wid = (blockIdx.x * blockDim.x + threadIdx.x) >> 5;
    int lane = threadIdx.x & 31;
    if (wid >= 2 * NN) return;
    bool back = wid >= NN;
    int n = back ? wid - NN : wid;
    const int* off = back ? g_off_out : g_off_in;
    const int* lst = back ? g_out_dst : g_in_src;
    const float* xl = back ? g_xl_b : g_xl_f;
    const float* al = back ? g_al_b : g_al_f;
    const float* ar = back ? g_ar_b : g_ar_f;
    const float* bias = back ? b_b : b_f;
    float* outp = back ? g_agg_b : g_agg_f;

    int h = lane >> 3;
    float arh = __ldg(&ar[n * 4 + h]);
    int beg = off[n];
    int end = (n == NN - 1) ? NEP : off[n + 1];

    float4 acc = make_float4(0.f, 0.f, 0.f, 0.f);
    float den = 0.f;
    int sj = (beg < end) ? __ldg(&lst[beg]) : 0;
    for (int j = beg; j < end; j++) {
        int s = sj;
        sj = (j + 1 < end) ? __ldg(&lst[j + 1]) : 0;
        float a = __ldg(&al[s * 4 + h]);
        float4 v = *(const float4*)(xl + (size_t)s * HC + lane * 4);
        float w = __expf(lrelu(a + arh));
        acc.x = fmaf(w, v.x, acc.x);
        acc.y = fmaf(w, v.y, acc.y);
        acc.z = fmaf(w, v.z, acc.z);
        acc.w = fmaf(w, v.w, acc.w);
        den += w;
    }
    float inv = 1.f / (den + 1e-16f);
    float4 b4 = *(const float4*)(bias + lane * 4);
    float4 o;
    o.x = fmaf(acc.x, inv, b4.x);
    o.y = fmaf(acc.y, inv, b4.y);
    o.z = fmaf(acc.z, inv, b4.z);
    o.w = fmaf(acc.w, inv, b4.w);
    *(float4*)(outp + (size_t)n * HC + lane * 4) = o;
}

// ---------------- launch ----------------
extern "C" void kernel_launch(void* const* d_in, const int* in_sizes, int n_in,
                              void* d_out, int out_size) {
    const float* x        = (const float*)d_in[0];
    const int*   ei       = (const int*)d_in[1];
    const float* W_f      = (const float*)d_in[2];
    const float* a_src_f  = (const float*)d_in[3];
    const float* a_dst_f  = (const float*)d_in[4];
    const float* b_f      = (const float*)d_in[5];
    const float* W_b      = (const float*)d_in[6];
    const float* a_src_b  = (const float*)d_in[7];
    const float* a_dst_b  = (const float*)d_in[8];
    const float* b_b      = (const float*)d_in[9];
    const float* W_fuse   = (const float*)d_in[10];
    const float* b_fuse   = (const float*)d_in[11];
    const float* gamma    = (const float*)d_in[12];
    const float* beta     = (const float*)d_in[13];
    const float* run_mean = (const float*)d_in[14];
    const float* run_var  = (const float*)d_in[15];
    float* out = (float*)d_out;

    pack_kernel<<<(NN + 255) / 256, 256>>>(b_fuse, gamma, beta, run_mean, run_var);
    hist_kernel<<<(NEP + 255) / 256, 256>>>(ei);
    scan_kernel<<<2, 1024>>>();
    scatter_kernel<<<(NEP + 255) / 256, 256>>>(ei);

    dim3 gg((NN + 127) / 128, 2);
    sgemm_kernel<0><<<gg, 256>>>(x, W_f, W_b, nullptr, a_src_f, a_dst_f, a_src_b, a_dst_b);

    gather_kernel<<<(2 * NN * 32 + 255) / 256, 256>>>(b_f, b_b);

    sgemm_kernel<1><<<gg, 256>>>(nullptr, W_fuse, nullptr, out,
                                 nullptr, nullptr, nullptr, nullptr);
}

// round 3
// speedup vs baseline: 1.4079x; 1.0494x over previous
#include <cuda_runtime.h>
#include <cuda_fp16.h>

// ---------------- problem constants ----------------
#define NN   50000
#define NE   1600000
#define NEP  (NE + NN)      // edges + self loops
#define KDIM 256
#define HC   128
#define NEG  0.2f

// ---------------- device scratch ----------------
__device__ __half g_xl_f[NN * HC];
__device__ __half g_xl_b[NN * HC];
__device__ float g_al_f[NN * 4];
__device__ float g_ar_f[NN * 4];
__device__ float g_al_b[NN * 4];
__device__ float g_ar_b[NN * 4];
__device__ float g_agg_f[NN * HC];
__device__ float g_agg_b[NN * HC];
__device__ float g_scale[256];
__device__ float g_shift[256];
// CSR scratch
__device__ int g_deg_in[NN];
__device__ int g_deg_out[NN];
__device__ int g_off_in[NN];
__device__ int g_off_out[NN];
__device__ int g_cur_in[NN];
__device__ int g_cur_out[NN];
__device__ int g_in_src[NEP];   // sorted by dst: source node per in-edge
__device__ int g_out_dst[NEP];  // sorted by src: dest node per out-edge

__device__ __forceinline__ float lrelu(float v) { return v > 0.f ? v : NEG * v; }

__device__ __forceinline__ unsigned long long pack2(float x, float y) {
    unsigned long long r;
    asm("mov.b64 %0, {%1, %2};" : "=l"(r) : "f"(x), "f"(y));
    return r;
}
__device__ __forceinline__ void unpack2(float& x, float& y, unsigned long long v) {
    asm("mov.b64 {%0, %1}, %2;" : "=f"(x), "=f"(y) : "l"(v));
}
__device__ __forceinline__ unsigned long long fma2(unsigned long long a, unsigned long long b,
                                                   unsigned long long c) {
    unsigned long long d;
    asm("fma.rn.f32x2 %0, %1, %2, %3;" : "=l"(d) : "l"(a), "l"(b), "l"(c));
    return d;
}

// ---------------- prep: BN constants + zero degree arrays ----------------
__global__ void pack_kernel(const float* __restrict__ b_fuse,
                            const float* __restrict__ gamma, const float* __restrict__ beta,
                            const float* __restrict__ mean, const float* __restrict__ var) {
    int t = blockIdx.x * blockDim.x + threadIdx.x;
    if (t < NN) { g_deg_in[t] = 0; g_deg_out[t] = 0; }
    if (t < 256) {
        float inv = rsqrtf(var[t] + 1e-5f);
        float sc = gamma[t] * inv;
        g_scale[t] = sc;
        g_shift[t] = beta[t] + (b_fuse[t] - mean[t]) * sc;
    }
}

// ---------------- CSR build ----------------
__global__ void hist_kernel(const int* __restrict__ ei) {
    int idx = blockIdx.x * blockDim.x + threadIdx.x;
    if (idx >= NEP) return;
    int s, d;
    if (idx < NE) { s = __ldg(&ei[idx]); d = __ldg(&ei[NE + idx]); }
    else          { s = d = idx - NE; }
    atomicAdd(&g_deg_in[d], 1);
    atomicAdd(&g_deg_out[s], 1);
}

__global__ void scan_kernel() {
    __shared__ int part[1024];
    int* deg = blockIdx.x ? g_deg_out : g_deg_in;
    int* off = blockIdx.x ? g_off_out : g_off_in;
    int* cur = blockIdx.x ? g_cur_out : g_cur_in;
    int t = threadIdx.x;
    const int CH = (NN + 1023) / 1024;  // 49
    int base = t * CH;
    int s = 0;
    for (int i = 0; i < CH; i++) { int idx = base + i; if (idx < NN) s += deg[idx]; }
    part[t] = s;
    __syncthreads();
    for (int d = 1; d < 1024; d <<= 1) {
        int v = (t >= d) ? part[t - d] : 0;
        __syncthreads();
        part[t] += v;
        __syncthreads();
    }
    int pre = (t == 0) ? 0 : part[t - 1];
    for (int i = 0; i < CH; i++) {
        int idx = base + i;
        if (idx < NN) { off[idx] = pre; cur[idx] = pre; pre += deg[idx]; }
    }
}

__global__ void scatter_kernel(const int* __restrict__ ei) {
    int idx = blockIdx.x * blockDim.x + threadIdx.x;
    if (idx >= NEP) return;
    int s, d;
    if (idx < NE) { s = __ldg(&ei[idx]); d = __ldg(&ei[NE + idx]); }
    else          { s = d = idx - NE; }
    int p = atomicAdd(&g_cur_in[d], 1);
    g_in_src[p] = s;
    int q = atomicAdd(&g_cur_out[s], 1);
    g_out_dst[q] = d;
}

// ---------------- SGEMM 128x128x16, 8x8/thread, f32x2 packed FMA ----------------
// MODE 0: C = x[NN,256] @ W_{f|b} (blockIdx.y selects) -> g_xl_* (fp16), fused al/ar
// MODE 1: C = concat(agg_f,agg_b) @ W_fuse -> BN+ReLU -> out
template <int MODE>
__global__ void __launch_bounds__(256)
sgemm_kernel(const float* __restrict__ A, const float* __restrict__ Bf,
             const float* __restrict__ Bb, float* __restrict__ Cout,
             const float* __restrict__ asrc_f, const float* __restrict__ adst_f,
             const float* __restrict__ asrc_b, const float* __restrict__ adst_b) {
    constexpr int BM = 128, BN = 128, BK = 16;
    __shared__ float As[BK][BM + 4];
    __shared__ float Bs[BK][BN + 4];
    const int tid = threadIdx.x;
    const int row0 = blockIdx.x * BM;
    const int col0 = blockIdx.y * BN;
    const int tx = tid & 15, ty = tid >> 4;

    unsigned long long acc2[8][4];
    const unsigned long long Z = pack2(0.f, 0.f);
#pragma unroll
    for (int i = 0; i < 8; i++)
#pragma unroll
        for (int j = 0; j < 4; j++) acc2[i][j] = Z;

    const float* Bp = (MODE == 0) ? ((blockIdx.y == 0) ? Bf : Bb) : Bf;

    for (int kt = 0; kt < KDIM; kt += BK) {
#pragma unroll
        for (int l = 0; l < 2; l++) {
            int v = tid + l * 256;
            int r = v >> 2;
            int c4 = (v & 3) << 2;
            int grow = row0 + r;
            float4 val = make_float4(0.f, 0.f, 0.f, 0.f);
            if (grow < NN) {
                int gk = kt + c4;
                if (MODE == 0) {
                    val = *(const float4*)(A + (size_t)grow * KDIM + gk);
                } else {
                    const float* ap = (gk < HC) ? (g_agg_f + (size_t)grow * HC + gk)
                                                : (g_agg_b + (size_t)grow * HC + (gk - HC));
                    val = *(const float4*)ap;
                }
            }
            As[c4 + 0][r] = val.x;
            As[c4 + 1][r] = val.y;
            As[c4 + 2][r] = val.z;
            As[c4 + 3][r] = val.w;
        }
#pragma unroll
        for (int l = 0; l < 2; l++) {
            int v = tid + l * 256;
            int r = v >> 5;
            int c4 = (v & 31) << 2;
            float4 bv;
            if (MODE == 0)
                bv = *(const float4*)(Bp + (size_t)(kt + r) * HC + c4);
            else
                bv = *(const float4*)(Bp + (size_t)(kt + r) * 256 + col0 + c4);
            *(float4*)&Bs[r][c4] = bv;
        }
        __syncthreads();
#pragma unroll
        for (int k = 0; k < BK; k++) {
            float4 a0 = *(const float4*)&As[k][ty * 8];
            float4 a1 = *(const float4*)&As[k][ty * 8 + 4];
            float4 b0 = *(const float4*)&Bs[k][tx * 8];
            float4 b1 = *(const float4*)&Bs[k][tx * 8 + 4];
            unsigned long long bp[4] = {pack2(b0.x, b0.y), pack2(b0.z, b0.w),
                                        pack2(b1.x, b1.y), pack2(b1.z, b1.w)};
            float am[8] = {a0.x, a0.y, a0.z, a0.w, a1.x, a1.y, a1.z, a1.w};
#pragma unroll
            for (int i = 0; i < 8; i++) {
                unsigned long long aa = pack2(am[i], am[i]);
#pragma unroll
                for (int j = 0; j < 4; j++) acc2[i][j] = fma2(aa, bp[j], acc2[i][j]);
            }
        }
        __syncthreads();
    }

    float accf[8][8];
#pragma unroll
    for (int i = 0; i < 8; i++)
#pragma unroll
        for (int j = 0; j < 4; j++) unpack2(accf[i][2 * j], accf[i][2 * j + 1], acc2[i][j]);

    if (MODE == 0) {
        __half* xl = (blockIdx.y == 0) ? g_xl_f : g_xl_b;
        const float* asrc = (blockIdx.y == 0) ? asrc_f : asrc_b;
        const float* adst = (blockIdx.y == 0) ? adst_f : adst_b;
        float* alp = (blockIdx.y == 0) ? g_al_f : g_al_b;
        float* arp = (blockIdx.y == 0) ? g_ar_f : g_ar_b;
        float av[8], dv[8];
        *(float4*)&av[0] = *(const float4*)(asrc + tx * 8);
        *(float4*)&av[4] = *(const float4*)(asrc + tx * 8 + 4);
        *(float4*)&dv[0] = *(const float4*)(adst + tx * 8);
        *(float4*)&dv[4] = *(const float4*)(adst + tx * 8 + 4);
        int head = tx >> 2;
#pragma unroll
        for (int i = 0; i < 8; i++) {
            int grow = row0 + ty * 8 + i;
            float ps = 0.f, pd = 0.f;
#pragma unroll
            for (int j = 0; j < 8; j++) {
                ps = fmaf(accf[i][j], av[j], ps);
                pd = fmaf(accf[i][j], dv[j], pd);
            }
            ps += __shfl_xor_sync(0xffffffffu, ps, 1);
            pd += __shfl_xor_sync(0xffffffffu, pd, 1);
            ps += __shfl_xor_sync(0xffffffffu, ps, 2);
            pd += __shfl_xor_sync(0xffffffffu, pd, 2);
            if (grow < NN) {
                __half2 h0 = __floats2half2_rn(accf[i][0], accf[i][1]);
                __half2 h1 = __floats2half2_rn(accf[i][2], accf[i][3]);
                __half2 h2 = __floats2half2_rn(accf[i][4], accf[i][5]);
                __half2 h3 = __floats2half2_rn(accf[i][6], accf[i][7]);
                uint4 pk = make_uint4(*(unsigned*)&h0, *(unsigned*)&h1,
                                      *(unsigned*)&h2, *(unsigned*)&h3);
                *(uint4*)(xl + (size_t)grow * HC + tx * 8) = pk;
                if ((tx & 3) == 0) {
                    alp[grow * 4 + head] = ps;
                    arp[grow * 4 + head] = pd;
                }
            }
        }
    } else {
#pragma unroll
        for (int i = 0; i < 8; i++) {
            int grow = row0 + ty * 8 + i;
            if (grow >= NN) continue;
#pragma unroll
            for (int j = 0; j < 8; j += 4) {
                int gcol = col0 + tx * 8 + j;
                float4 sc = *(const float4*)(g_scale + gcol);
                float4 sh = *(const float4*)(g_shift + gcol);
                float4 v;
                v.x = fmaxf(fmaf(accf[i][j + 0], sc.x, sh.x), 0.f);
                v.y = fmaxf(fmaf(accf[i][j + 1], sc.y, sh.y), 0.f);
                v.z = fmaxf(fmaf(accf[i][j + 2], sc.z, sh.z), 0.f);
                v.w = fmaxf(fmaf(accf[i][j + 3], sc.w, sh.w), 0.f);
                *(float4*)(Cout + (size_t)grow * 256 + gcol) = v;
            }
        }
    }
}

// ---------------- gather: warp per (node, direction), single pass ----------------
__global__ void __launch_bounds__(256)
gather_kernel(const float* __restrict__ b_f, const float* __restrict__ b_b) {
    int wid = (blockIdx.x * blockDim.x + threadIdx.x) >> 5;
    int lane = threadIdx.x & 31;
    if (wid >= 2 * NN) return;
    bool back = wid >= NN;
    int n = back ? wid - NN : wid;
    const int* off = back ? g_off_out : g_off_in;
    const int* lst = back ? g_out_dst : g_in_src;
    const __half* xl = back ? g_xl_b : g_xl_f;
    const float* al = back ? g_al_b : g_al_f;
    const float* ar = back ? g_ar_b : g_ar_f;
    const float* bias = back ? b_b : b_f;
    float* outp = back ? g_agg_b : g_agg_f;

    int h = lane >> 3;
    float arh = __ldg(&ar[n * 4 + h]);
    int beg = off[n];
    int end = (n == NN - 1) ? NEP : off[n + 1];

    float4 acc = make_float4(0.f, 0.f, 0.f, 0.f);
    float den = 0.f;
    int sj = (beg < end) ? __ldg(&lst[beg]) : 0;
    for (int j = beg; j < end; j++) {
        int s = sj;
        sj = (j + 1 < end) ? __ldg(&lst[j + 1]) : 0;
        float a = __ldg(&al[s * 4 + h]);
        uint2 raw = *(const uint2*)(xl + (size_t)s * HC + lane * 4);
        float2 v01 = __half22float2(*(__half2*)&raw.x);
        float2 v23 = __half22float2(*(__half2*)&raw.y);
        float w = __expf(lrelu(a + arh));
        acc.x = fmaf(w, v01.x, acc.x);
        acc.y = fmaf(w, v01.y, acc.y);
        acc.z = fmaf(w, v23.x, acc.z);
        acc.w = fmaf(w, v23.y, acc.w);
        den += w;
    }
    float inv = 1.f / (den + 1e-16f);
    float4 b4 = *(const float4*)(bias + lane * 4);
    float4 o;
    o.x = fmaf(acc.x, inv, b4.x);
    o.y = fmaf(acc.y, inv, b4.y);
    o.z = fmaf(acc.z, inv, b4.z);
    o.w = fmaf(acc.w, inv, b4.w);
    *(float4*)(outp + (size_t)n * HC + lane * 4) = o;
}

// ---------------- launch ----------------
extern "C" void kernel_launch(void* const* d_in, const int* in_sizes, int n_in,
                              void* d_out, int out_size) {
    const float* x        = (const float*)d_in[0];
    const int*   ei       = (const int*)d_in[1];
    const float* W_f      = (const float*)d_in[2];
    const float* a_src_f  = (const float*)d_in[3];
    const float* a_dst_f  = (const float*)d_in[4];
    const float* b_f      = (const float*)d_in[5];
    const float* W_b      = (const float*)d_in[6];
    const float* a_src_b  = (const float*)d_in[7];
    const float* a_dst_b  = (const float*)d_in[8];
    const float* b_b      = (const float*)d_in[9];
    const float* W_fuse   = (const float*)d_in[10];
    const float* b_fuse   = (const float*)d_in[11];
    const float* gamma    = (const float*)d_in[12];
    const float* beta     = (const float*)d_in[13];
    const float* run_mean = (const float*)d_in[14];
    const float* run_var  = (const float*)d_in[15];
    float* out = (float*)d_out;

    // side stream for the CSR build (depends only on edge_index) so the graph
    // runs it concurrently with GEMM0 (depends only on x / W). Created once,
    // outside capture (first call is the uncaptured correctness run).
    static cudaStream_t s_side = nullptr;
    static cudaEvent_t ev_fork = nullptr, ev_join = nullptr;
    if (!s_side) {
        cudaStreamCreateWithFlags(&s_side, cudaStreamNonBlocking);
        cudaEventCreateWithFlags(&ev_fork, cudaEventDisableTiming);
        cudaEventCreateWithFlags(&ev_join, cudaEventDisableTiming);
    }

    cudaEventRecord(ev_fork, 0);
    cudaStreamWaitEvent(s_side, ev_fork, 0);

    pack_kernel<<<(NN + 255) / 256, 256, 0, s_side>>>(b_fuse, gamma, beta, run_mean, run_var);
    hist_kernel<<<(NEP + 255) / 256, 256, 0, s_side>>>(ei);
    scan_kernel<<<2, 1024, 0, s_side>>>();
    scatter_kernel<<<(NEP + 255) / 256, 256, 0, s_side>>>(ei);
    cudaEventRecord(ev_join, s_side);

    dim3 gg((NN + 127) / 128, 2);
    sgemm_kernel<0><<<gg, 256>>>(x, W_f, W_b, nullptr, a_src_f, a_dst_f, a_src_b, a_dst_b);

    cudaStreamWaitEvent(0, ev_join, 0);

    gather_kernel<<<(2 * NN * 32 + 255) / 256, 256>>>(b_f, b_b);

    sgemm_kernel<1><<<gg, 256>>>(nullptr, W_fuse, nullptr, out,
                                 nullptr, nullptr, nullptr, nullptr);
}

// round 4
// speedup vs baseline: 2.2526x; 1.5999x over previous
#include <cuda_runtime.h>
#include <cuda_fp16.h>
#include <mma.h>
using namespace nvcuda;

// ---------------- problem constants ----------------
#define NN   50000
#define NE   1600000
#define NEP  (NE + NN)      // edges + self loops
#define KDIM 256
#define HC   128
#define NEG  0.2f

// ---------------- device scratch ----------------
__device__ __half g_x_h[NN * KDIM];       // x in fp16
__device__ __half g_Bcat_h[KDIM * 256];   // [k][j]: j<128 -> W_f, else W_b
__device__ __half g_Wfuse_h[KDIM * 256];
__device__ __half g_xl_f[NN * HC];
__device__ __half g_xl_b[NN * HC];
__device__ __half g_agg_h[NN * 256];      // concat(agg_f, agg_b) fp16
__device__ float g_al_f[NN * 4];
__device__ float g_ar_f[NN * 4];
__device__ float g_al_b[NN * 4];
__device__ float g_ar_b[NN * 4];
__device__ float g_scale[256];
__device__ float g_shift[256];
// CSR scratch
__device__ int g_deg_in[NN];
__device__ int g_deg_out[NN];
__device__ int g_off_in[NN];
__device__ int g_off_out[NN];
__device__ int g_cur_in[NN];
__device__ int g_cur_out[NN];
__device__ int g_in_src[NEP];
__device__ int g_out_dst[NEP];

__device__ __forceinline__ float lrelu(float v) { return v > 0.f ? v : NEG * v; }

// ---------------- prep ----------------
__global__ void pack_kernel(const float* __restrict__ b_fuse,
                            const float* __restrict__ gamma, const float* __restrict__ beta,
                            const float* __restrict__ mean, const float* __restrict__ var) {
    int t = blockIdx.x * blockDim.x + threadIdx.x;
    if (t < NN) { g_deg_in[t] = 0; g_deg_out[t] = 0; }
    if (t < 256) {
        float inv = rsqrtf(var[t] + 1e-5f);
        float sc = gamma[t] * inv;
        g_scale[t] = sc;
        g_shift[t] = beta[t] + (b_fuse[t] - mean[t]) * sc;
    }
}

__global__ void conv_w_kernel(const float* __restrict__ Wf, const float* __restrict__ Wb,
                              const float* __restrict__ Wfu) {
    int t = blockIdx.x * blockDim.x + threadIdx.x;
    if (t < KDIM * 256) {
        int k = t >> 8, j = t & 255;
        float v = (j < HC) ? Wf[k * HC + j] : Wb[k * HC + (j - HC)];
        g_Bcat_h[t] = __float2half_rn(v);
        g_Wfuse_h[t] = __float2half_rn(Wfu[t]);
    }
}

__global__ void conv_x_kernel(const float* __restrict__ x) {
    int t = blockIdx.x * blockDim.x + threadIdx.x;
    if (t >= NN * KDIM / 8) return;
    float4 a = *(const float4*)(x + t * 8);
    float4 b = *(const float4*)(x + t * 8 + 4);
    __half2 h0 = __floats2half2_rn(a.x, a.y);
    __half2 h1 = __floats2half2_rn(a.z, a.w);
    __half2 h2 = __floats2half2_rn(b.x, b.y);
    __half2 h3 = __floats2half2_rn(b.z, b.w);
    *(uint4*)(g_x_h + t * 8) = make_uint4(*(unsigned*)&h0, *(unsigned*)&h1,
                                          *(unsigned*)&h2, *(unsigned*)&h3);
}

// ---------------- CSR build ----------------
__global__ void hist_kernel(const int* __restrict__ ei) {
    int idx = blockIdx.x * blockDim.x + threadIdx.x;
    if (idx >= NEP) return;
    int s, d;
    if (idx < NE) { s = __ldg(&ei[idx]); d = __ldg(&ei[NE + idx]); }
    else          { s = d = idx - NE; }
    atomicAdd(&g_deg_in[d], 1);
    atomicAdd(&g_deg_out[s], 1);
}

__global__ void scan_kernel() {
    __shared__ int part[1024];
    int* deg = blockIdx.x ? g_deg_out : g_deg_in;
    int* off = blockIdx.x ? g_off_out : g_off_in;
    int* cur = blockIdx.x ? g_cur_out : g_cur_in;
    int t = threadIdx.x;
    const int CH = (NN + 1023) / 1024;
    int base = t * CH;
    int s = 0;
    for (int i = 0; i < CH; i++) { int idx = base + i; if (idx < NN) s += deg[idx]; }
    part[t] = s;
    __syncthreads();
    for (int d = 1; d < 1024; d <<= 1) {
        int v = (t >= d) ? part[t - d] : 0;
        __syncthreads();
        part[t] += v;
        __syncthreads();
    }
    int pre = (t == 0) ? 0 : part[t - 1];
    for (int i = 0; i < CH; i++) {
        int idx = base + i;
        if (idx < NN) { off[idx] = pre; cur[idx] = pre; pre += deg[idx]; }
    }
}

__global__ void scatter_kernel(const int* __restrict__ ei) {
    int idx = blockIdx.x * blockDim.x + threadIdx.x;
    if (idx >= NEP) return;
    int s, d;
    if (idx < NE) { s = __ldg(&ei[idx]); d = __ldg(&ei[NE + idx]); }
    else          { s = d = idx - NE; }
    int p = atomicAdd(&g_cur_in[d], 1);
    g_in_src[p] = s;
    int q = atomicAdd(&g_cur_out[s], 1);
    g_out_dst[q] = d;
}

// ---------------- HMMA GEMM: 128x128 tile, BK=32, 8 warps (4M x 2N) ----------------
// MODE 0: C = g_x_h @ g_Bcat_h; blockIdx.y = direction -> xl fp16 + al/ar epilogue
// MODE 1: C = g_agg_h @ g_Wfuse_h -> BN+ReLU -> out
#define A_LDM 40
#define B_LDM 136
#define C_LDM 132
#define SMEM_SZ (128 * C_LDM * 4)   // 67584, also covers A+B stage (18944)

template <int MODE>
__global__ void __launch_bounds__(256)
hgemm_kernel(float* __restrict__ Cout,
             const float* __restrict__ asrc_f, const float* __restrict__ adst_f,
             const float* __restrict__ asrc_b, const float* __restrict__ adst_b) {
    extern __shared__ char sm_raw[];
    __half* As = (__half*)sm_raw;                        // [128][A_LDM]
    __half* Bs = (__half*)(sm_raw + 128 * A_LDM * 2);    // [32][B_LDM]
    float* Cs = (float*)sm_raw;                          // [128][C_LDM] (after loop)

    const int tid = threadIdx.x;
    const int warp = tid >> 5;
    const int wm = warp & 3;    // 32-row strip
    const int wn = warp >> 2;   // 64-col strip
    const int row0 = blockIdx.x * 128;
    const int dir = blockIdx.y;
    const int colB = dir * 128;

    const __half* Ag = (MODE == 0) ? g_x_h : g_agg_h;
    const __half* Bg = (MODE == 0) ? g_Bcat_h : g_Wfuse_h;

    wmma::fragment<wmma::accumulator, 16, 16, 16, float> acc[2][4];
#pragma unroll
    for (int i = 0; i < 2; i++)
#pragma unroll
        for (int j = 0; j < 4; j++) wmma::fill_fragment(acc[i][j], 0.f);

    for (int kt = 0; kt < KDIM; kt += 32) {
        // A tile: 128 rows x 32 cols, 8-half chunks: 512 chunks / 256 thr = 2
#pragma unroll
        for (int l = 0; l < 2; l++) {
            int c = tid + l * 256;
            int r = c >> 2;
            int c8 = (c & 3) * 8;
            int grow = row0 + r;
            uint4 v = make_uint4(0, 0, 0, 0);
            if (grow < NN) v = *(const uint4*)(Ag + (size_t)grow * KDIM + kt + c8);
            *(uint4*)(As + r * A_LDM + c8) = v;
        }
        // B tile: 32 rows x 128 cols
#pragma unroll
        for (int l = 0; l < 2; l++) {
            int c = tid + l * 256;
            int r = c >> 4;
            int c8 = (c & 15) * 8;
            *(uint4*)(Bs + r * B_LDM + c8) =
                *(const uint4*)(Bg + (size_t)(kt + r) * 256 + colB + c8);
        }
        __syncthreads();
#pragma unroll
        for (int kk = 0; kk < 32; kk += 16) {
            wmma::fragment<wmma::matrix_a, 16, 16, 16, __half, wmma::row_major> af[2];
            wmma::fragment<wmma::matrix_b, 16, 16, 16, __half, wmma::row_major> bf[4];
#pragma unroll
            for (int i = 0; i < 2; i++)
                wmma::load_matrix_sync(af[i], As + (wm * 32 + i * 16) * A_LDM + kk, A_LDM);
#pragma unroll
            for (int j = 0; j < 4; j++)
                wmma::load_matrix_sync(bf[j], Bs + kk * B_LDM + wn * 64 + j * 16, B_LDM);
#pragma unroll
            for (int i = 0; i < 2; i++)
#pragma unroll
                for (int j = 0; j < 4; j++)
                    wmma::mma_sync(acc[i][j], af[i], bf[j], acc[i][j]);
        }
        __syncthreads();
    }

    // stage C tile to smem
#pragma unroll
    for (int i = 0; i < 2; i++)
#pragma unroll
        for (int j = 0; j < 4; j++)
            wmma::store_matrix_sync(Cs + (wm * 32 + i * 16) * C_LDM + wn * 64 + j * 16,
                                    acc[i][j], C_LDM, wmma::mem_row_major);
    __syncthreads();

    const int r = tid >> 1;
    const int c0 = (tid & 1) * 64;
    const int grow = row0 + r;
    if (grow >= NN) return;
    const float* Crow = Cs + r * C_LDM + c0;

    if (MODE == 0) {
        __half* xl = dir ? g_xl_b : g_xl_f;
        const float* asrc = dir ? asrc_b : asrc_f;
        const float* adst = dir ? adst_b : adst_f;
        float* alp = dir ? g_al_b : g_al_f;
        float* arp = dir ? g_ar_b : g_ar_f;
#pragma unroll
        for (int hh = 0; hh < 2; hh++) {
            int head = (tid & 1) * 2 + hh;
            float ps = 0.f, pd = 0.f;
#pragma unroll
            for (int c = 0; c < 32; c++) {
                float v = Crow[hh * 32 + c];
                ps = fmaf(v, __ldg(&asrc[head * 32 + c]), ps);
                pd = fmaf(v, __ldg(&adst[head * 32 + c]), pd);
            }
            alp[grow * 4 + head] = ps;
            arp[grow * 4 + head] = pd;
        }
#pragma unroll
        for (int c = 0; c < 64; c += 8) {
            __half2 h0 = __floats2half2_rn(Crow[c + 0], Crow[c + 1]);
            __half2 h1 = __floats2half2_rn(Crow[c + 2], Crow[c + 3]);
            __half2 h2 = __floats2half2_rn(Crow[c + 4], Crow[c + 5]);
            __half2 h3 = __floats2half2_rn(Crow[c + 6], Crow[c + 7]);
            *(uint4*)(xl + (size_t)grow * HC + c0 + c) =
                make_uint4(*(unsigned*)&h0, *(unsigned*)&h1,
                           *(unsigned*)&h2, *(unsigned*)&h3);
        }
    } else {
        const int colC = dir * 128 + c0;
#pragma unroll
        for (int j = 0; j < 64; j += 4) {
            int gc = colC + j;
            float4 v = *(const float4*)(Crow + j);
            float4 sc = *(const float4*)(g_scale + gc);
            float4 sh = *(const float4*)(g_shift + gc);
            v.x = fmaxf(fmaf(v.x, sc.x, sh.x), 0.f);
            v.y = fmaxf(fmaf(v.y, sc.y, sh.y), 0.f);
            v.z = fmaxf(fmaf(v.z, sc.z, sh.z), 0.f);
            v.w = fmaxf(fmaf(v.w, sc.w, sh.w), 0.f);
            *(float4*)(Cout + (size_t)grow * 256 + gc) = v;
        }
    }
}

// ---------------- gather: warp per (node, direction) ----------------
__global__ void __launch_bounds__(256)
gather_kernel(const float* __restrict__ b_f, const float* __restrict__ b_b) {
    int wid = (blockIdx.x * blockDim.x + threadIdx.x) >> 5;
    int lane = threadIdx.x & 31;
    if (wid >= 2 * NN) return;
    bool back = wid >= NN;
    int n = back ? wid - NN : wid;
    const int* off = back ? g_off_out : g_off_in;
    const int* lst = back ? g_out_dst : g_in_src;
    const __half* xl = back ? g_xl_b : g_xl_f;
    const float* al = back ? g_al_b : g_al_f;
    const float* ar = back ? g_ar_b : g_ar_f;
    const float* bias = back ? b_b : b_f;

    int h = lane >> 3;
    float arh = __ldg(&ar[n * 4 + h]);
    int beg = off[n];
    int end = (n == NN - 1) ? NEP : off[n + 1];

    float4 acc = make_float4(0.f, 0.f, 0.f, 0.f);
    float den = 0.f;
    int sj = (beg < end) ? __ldg(&lst[beg]) : 0;
    for (int j = beg; j < end; j++) {
        int s = sj;
        sj = (j + 1 < end) ? __ldg(&lst[j + 1]) : 0;
        float a = __ldg(&al[s * 4 + h]);
        uint2 raw = *(const uint2*)(xl + (size_t)s * HC + lane * 4);
        float2 v01 = __half22float2(*(__half2*)&raw.x);
        float2 v23 = __half22float2(*(__half2*)&raw.y);
        float w = __expf(lrelu(a + arh));
        acc.x = fmaf(w, v01.x, acc.x);
        acc.y = fmaf(w, v01.y, acc.y);
        acc.z = fmaf(w, v23.x, acc.z);
        acc.w = fmaf(w, v23.y, acc.w);
        den += w;
    }
    float inv = 1.f / (den + 1e-16f);
    float4 b4 = *(const float4*)(bias + lane * 4);
    float4 o;
    o.x = fmaf(acc.x, inv, b4.x);
    o.y = fmaf(acc.y, inv, b4.y);
    o.z = fmaf(acc.z, inv, b4.z);
    o.w = fmaf(acc.w, inv, b4.w);
    __half2 p0 = __floats2half2_rn(o.x, o.y);
    __half2 p1 = __floats2half2_rn(o.z, o.w);
    *(uint2*)(g_agg_h + (size_t)n * 256 + (back ? 128 : 0) + lane * 4) =
        make_uint2(*(unsigned*)&p0, *(unsigned*)&p1);
}

// ---------------- launch ----------------
extern "C" void kernel_launch(void* const* d_in, const int* in_sizes, int n_in,
                              void* d_out, int out_size) {
    const float* x        = (const float*)d_in[0];
    const int*   ei       = (const int*)d_in[1];
    const float* W_f      = (const float*)d_in[2];
    const float* a_src_f  = (const float*)d_in[3];
    const float* a_dst_f  = (const float*)d_in[4];
    const float* b_f      = (const float*)d_in[5];
    const float* W_b      = (const float*)d_in[6];
    const float* a_src_b  = (const float*)d_in[7];
    const float* a_dst_b  = (const float*)d_in[8];
    const float* b_b      = (const float*)d_in[9];
    const float* W_fuse   = (const float*)d_in[10];
    const float* b_fuse   = (const float*)d_in[11];
    const float* gamma    = (const float*)d_in[12];
    const float* beta     = (const float*)d_in[13];
    const float* run_mean = (const float*)d_in[14];
    const float* run_var  = (const float*)d_in[15];
    float* out = (float*)d_out;

    static cudaStream_t s_side = nullptr;
    static cudaEvent_t ev_fork = nullptr, ev_join = nullptr;
    if (!s_side) {
        cudaStreamCreateWithFlags(&s_side, cudaStreamNonBlocking);
        cudaEventCreateWithFlags(&ev_fork, cudaEventDisableTiming);
        cudaEventCreateWithFlags(&ev_join, cudaEventDisableTiming);
        cudaFuncSetAttribute(hgemm_kernel<0>, cudaFuncAttributeMaxDynamicSharedMemorySize, SMEM_SZ);
        cudaFuncSetAttribute(hgemm_kernel<1>, cudaFuncAttributeMaxDynamicSharedMemorySize, SMEM_SZ);
    }

    cudaEventRecord(ev_fork, 0);
    cudaStreamWaitEvent(s_side, ev_fork, 0);

    // side stream: CSR build (depends only on edge_index)
    pack_kernel<<<(NN + 255) / 256, 256, 0, s_side>>>(b_fuse, gamma, beta, run_mean, run_var);
    hist_kernel<<<(NEP + 255) / 256, 256, 0, s_side>>>(ei);
    scan_kernel<<<2, 1024, 0, s_side>>>();
    scatter_kernel<<<(NEP + 255) / 256, 256, 0, s_side>>>(ei);
    cudaEventRecord(ev_join, s_side);

    // main stream
    conv_w_kernel<<<(KDIM * 256 + 255) / 256, 256>>>(W_f, W_b, W_fuse);
    conv_x_kernel<<<(NN * KDIM / 8 + 255) / 256, 256>>>(x);

    dim3 gg((NN + 127) / 128, 2);
    hgemm_kernel<0><<<gg, 256, SMEM_SZ>>>(nullptr, a_src_f, a_dst_f, a_src_b, a_dst_b);

    cudaStreamWaitEvent(0, ev_join, 0);
    gather_kernel<<<(2 * NN * 32 + 255) / 256, 256>>>(b_f, b_b);

    hgemm_kernel<1><<<gg, 256, SMEM_SZ>>>(out, nullptr, nullptr, nullptr, nullptr);
}